// round 1
// baseline (speedup 1.0000x reference)
#include <cuda_runtime.h>
#include <cuda_bf16.h>
#include <cstdint>

// Problem constants
#define Bq      32
#define Sq      4096
#define Dq      64
#define Pq      8
#define STRIDEq 4
#define Hq      512
#define Tq      1023          // (S - P) / STRIDE + 1
#define Mrows   (Bq * Tq)     // 32736
#define Kdim    (Pq * Dq)     // 512

// -------------------------------------------------------------------------
// Kernel 1: build tokens (patch gather) + write token_lengths.
// tokens[b,t,:] = x[b, t*4 .. t*4+7, :] flattened if t < n_tok[b] else 0.
// One block per (b,t) row, 128 threads, one float4 each (512 floats).
// -------------------------------------------------------------------------
__global__ void build_tokens_kernel(const float* __restrict__ x,
                                    const int*   __restrict__ lengths,
                                    float* __restrict__ tok,
                                    float* __restrict__ out_len)
{
    const int row = blockIdx.x;           // 0 .. Mrows-1
    const int b   = row / Tq;
    const int t   = row - b * Tq;

    const int len  = lengths[b];
    const int ntok = (len - Pq) / STRIDEq + 1;   // len >= P always per setup

    const int i = threadIdx.x;            // 0..127 (float4 index in 512-row)
    float4 v = make_float4(0.f, 0.f, 0.f, 0.f);
    if (t < ntok) {
        const int p  = i >> 4;            // (i*4)/64
        const int d4 = i & 15;            // float4 index within D=64
        const float4* src = reinterpret_cast<const float4*>(
            x + ((size_t)b * Sq + (size_t)t * STRIDEq + p) * Dq);
        v = src[d4];
    }
    reinterpret_cast<float4*>(tok + (size_t)row * Kdim)[i] = v;

    if (row == 0 && threadIdx.x < Bq) {
        const int lb = lengths[threadIdx.x];
        out_len[threadIdx.x] = (float)((lb - Pq) / STRIDEq + 1);
    }
}

// -------------------------------------------------------------------------
// Kernel 2: SGEMM  C[M, 512] = A[M, 512] @ W[512, 512] + bias
// Classic 128x128x8 register-tiled fp32 GEMM. 256 threads, 8x8 per thread.
// grid = (H/BN = 4, ceil(M/BM) = 256)
// -------------------------------------------------------------------------
__global__ __launch_bounds__(256, 2)
void gemm_bias_kernel(const float* __restrict__ A,
                      const float* __restrict__ Wm,
                      const float* __restrict__ bias,
                      float* __restrict__ C)
{
    constexpr int BM = 128, BN = 128, BK = 8, TM = 8, TN = 8;

    __shared__ float As[BK][BM];   // A tile, transposed for broadcast reads
    __shared__ float Bs[BK][BN];

    const int tid = threadIdx.x;
    const int m0  = blockIdx.y * BM;
    const int n0  = blockIdx.x * BN;

    // A-load mapping: 256 threads * 1 float4 = 128 rows * 8 k (2 float4/row)
    const int a_row = tid >> 1;
    const int a_k   = (tid & 1) * 4;
    // B-load mapping: 8 k-rows * 128 cols (32 float4/row)
    const int b_k   = tid >> 5;
    const int b_n   = (tid & 31) * 4;

    // compute mapping: 16 x 16 thread grid, each 8x8 micro-tile
    const int tm = (tid >> 4) * TM;
    const int tn = (tid & 15) * TN;

    float acc[TM][TN] = {};
    float ar[TM], br[TN];

    for (int k0 = 0; k0 < Kdim; k0 += BK) {
        // ---- load A tile (guard M) ----
        float4 av = make_float4(0.f, 0.f, 0.f, 0.f);
        const int gm = m0 + a_row;
        if (gm < Mrows)
            av = *reinterpret_cast<const float4*>(A + (size_t)gm * Kdim + k0 + a_k);
        As[a_k + 0][a_row] = av.x;
        As[a_k + 1][a_row] = av.y;
        As[a_k + 2][a_row] = av.z;
        As[a_k + 3][a_row] = av.w;

        // ---- load B tile ----
        const float4 bv = *reinterpret_cast<const float4*>(
            Wm + (size_t)(k0 + b_k) * Hq + n0 + b_n);
        *reinterpret_cast<float4*>(&Bs[b_k][b_n]) = bv;

        __syncthreads();

        #pragma unroll
        for (int k = 0; k < BK; k++) {
            #pragma unroll
            for (int i = 0; i < TM; i++) ar[i] = As[k][tm + i];
            #pragma unroll
            for (int j = 0; j < TN; j++) br[j] = Bs[k][tn + j];
            #pragma unroll
            for (int i = 0; i < TM; i++)
                #pragma unroll
                for (int j = 0; j < TN; j++)
                    acc[i][j] += ar[i] * br[j];
        }
        __syncthreads();
    }

    // epilogue: + bias, store
    float bl[TN];
    #pragma unroll
    for (int j = 0; j < TN; j++) bl[j] = bias[n0 + tn + j];

    #pragma unroll
    for (int i = 0; i < TM; i++) {
        const int gm = m0 + tm + i;
        if (gm >= Mrows) continue;
        float* crow = C + (size_t)gm * Hq + n0 + tn;
        #pragma unroll
        for (int j = 0; j < TN; j += 4) {
            float4 o;
            o.x = acc[i][j + 0] + bl[j + 0];
            o.y = acc[i][j + 1] + bl[j + 1];
            o.z = acc[i][j + 2] + bl[j + 2];
            o.w = acc[i][j + 3] + bl[j + 3];
            *reinterpret_cast<float4*>(crow + j) = o;
        }
    }
}

// -------------------------------------------------------------------------
// Kernel 3: in-place RMSNorm per row of 512: h = h / sqrt(mean(h^2)+eps) * scale
// One block (128 threads, float4 each) per row.
// -------------------------------------------------------------------------
__global__ void rmsnorm_kernel(float* __restrict__ h,
                               const float* __restrict__ scale)
{
    const int row = blockIdx.x;
    float4* hp = reinterpret_cast<float4*>(h + (size_t)row * Hq);
    const int i = threadIdx.x;   // 0..127

    float4 v = hp[i];
    float ss = v.x * v.x + v.y * v.y + v.z * v.z + v.w * v.w;

    // reduce over 128 threads (4 warps)
    #pragma unroll
    for (int o = 16; o > 0; o >>= 1)
        ss += __shfl_down_sync(0xffffffffu, ss, o);

    __shared__ float red[4];
    if ((i & 31) == 0) red[i >> 5] = ss;
    __syncthreads();

    const float tot = red[0] + red[1] + red[2] + red[3];
    const float inv = rsqrtf(tot * (1.0f / (float)Hq) + 1e-6f);

    const float4 s = reinterpret_cast<const float4*>(scale)[i];
    v.x *= inv * s.x;
    v.y *= inv * s.y;
    v.z *= inv * s.z;
    v.w *= inv * s.w;
    hp[i] = v;
}

// -------------------------------------------------------------------------
// Launch. Output layout (fp32): [hidden M*512][token_lengths 32][tokens M*512]
// -------------------------------------------------------------------------
extern "C" void kernel_launch(void* const* d_in, const int* in_sizes, int n_in,
                              void* d_out, int out_size)
{
    const float* x       = (const float*)d_in[0];
    const int*   lengths = (const int*)  d_in[1];
    const float* W       = (const float*)d_in[2];
    const float* bias    = (const float*)d_in[3];
    const float* scale   = (const float*)d_in[4];

    float* out        = (float*)d_out;
    float* out_hidden = out;
    float* out_len    = out + (size_t)Mrows * Hq;
    float* out_tokens = out + (size_t)Mrows * Hq + Bq;

    // 1) patch gather -> tokens region (+ token_lengths)
    build_tokens_kernel<<<Mrows, 128>>>(x, lengths, out_tokens, out_len);

    // 2) GEMM + bias -> hidden region (pre-norm)
    dim3 ggrid(Hq / 128, (Mrows + 127) / 128);
    gemm_bias_kernel<<<ggrid, 256>>>(out_tokens, W, bias, out_hidden);

    // 3) in-place RMSNorm on hidden region
    rmsnorm_kernel<<<Mrows, 128>>>(out_hidden, scale);
}

// round 3
// speedup vs baseline: 2.5213x; 2.5213x over previous
#include <cuda_runtime.h>
#include <cuda_bf16.h>
#include <cstdint>

// ---------------- problem constants ----------------
#define Bq      32
#define Sq      4096
#define Dq      64
#define Pq      8
#define STRIDEq 4
#define Hq      512
#define Tq      1023
#define Mrows   (Bq * Tq)     // 32736
#define Mpad    32768
#define Kdim    512

// ---------------- device-global scratch (allocation-free rule) ----------
__device__ __align__(256) __nv_bfloat16 g_Ah[(size_t)Mpad * Kdim];
__device__ __align__(256) __nv_bfloat16 g_Al[(size_t)Mpad * Kdim];
__device__ __align__(256) __nv_bfloat16 g_Wh[Kdim * Hq];   // hi split, [k][h]
__device__ __align__(256) __nv_bfloat16 g_Wl[Kdim * Hq];   // lo split, [k][h]

// ---------------- PTX helpers (plain sm_80-class PTX only) -------------
__device__ __forceinline__ uint32_t smem_u32(const void* p) {
    uint32_t a;
    asm("{ .reg .u64 t; cvta.to.shared.u64 t, %1; cvt.u32.u64 %0, t; }" : "=r"(a) : "l"(p));
    return a;
}

#define CP_ASYNC16(dst, src) \
    asm volatile("cp.async.cg.shared.global [%0], [%1], 16;" \
                 :: "r"((uint32_t)(dst)), "l"(__cvta_generic_to_global(src)) : "memory")
#define CP_COMMIT()  asm volatile("cp.async.commit_group;" ::: "memory")
#define CP_WAIT1()   asm volatile("cp.async.wait_group 1;" ::: "memory")
#define CP_WAIT0()   asm volatile("cp.async.wait_group 0;" ::: "memory")

#define LDSM4(r, addr) \
    asm volatile("ldmatrix.sync.aligned.m8n8.x4.shared.b16 {%0,%1,%2,%3}, [%4];" \
                 : "=r"((r)[0]), "=r"((r)[1]), "=r"((r)[2]), "=r"((r)[3]) : "r"(addr))
#define LDSM4T(r, addr) \
    asm volatile("ldmatrix.sync.aligned.m8n8.x4.trans.shared.b16 {%0,%1,%2,%3}, [%4];" \
                 : "=r"((r)[0]), "=r"((r)[1]), "=r"((r)[2]), "=r"((r)[3]) : "r"(addr))

#define MMA16816(d, a, b0_, b1_) \
    asm volatile("mma.sync.aligned.m16n8k16.row.col.f32.bf16.bf16.f32 " \
                 "{%0,%1,%2,%3}, {%4,%5,%6,%7}, {%8,%9}, {%0,%1,%2,%3};" \
                 : "+f"((d)[0]), "+f"((d)[1]), "+f"((d)[2]), "+f"((d)[3]) \
                 : "r"((a)[0]), "r"((a)[1]), "r"((a)[2]), "r"((a)[3]), \
                   "r"(b0_), "r"(b1_))

__device__ __forceinline__ uint32_t pack_bf2(__nv_bfloat16 a, __nv_bfloat16 b) {
    __nv_bfloat162 t = __halves2bfloat162(a, b);
    return *reinterpret_cast<uint32_t*>(&t);
}

// -------------------------------------------------------------------------
// Kernel 1: gather tokens + bf16 hi/lo split of A. Grid Mpad, 128 thr.
// -------------------------------------------------------------------------
__global__ void gather_split_kernel(const float* __restrict__ x,
                                    const int*   __restrict__ lengths,
                                    float* __restrict__ tok,
                                    float* __restrict__ out_len)
{
    const int row = blockIdx.x;
    const int i   = threadIdx.x;          // float4 index within 512-row
    float4 v = make_float4(0.f, 0.f, 0.f, 0.f);

    if (row < Mrows) {
        const int b = row / Tq;
        const int t = row - b * Tq;
        const int ntok = (lengths[b] - Pq) / STRIDEq + 1;
        if (t < ntok) {
            const int p  = i >> 4;
            const int d4 = i & 15;
            v = reinterpret_cast<const float4*>(
                    x + ((size_t)b * Sq + (size_t)t * STRIDEq + p) * Dq)[d4];
        }
        reinterpret_cast<float4*>(tok + (size_t)row * Kdim)[i] = v;
        if (row == 0 && i < Bq)
            out_len[i] = (float)((lengths[i] - Pq) / STRIDEq + 1);
    }

    __nv_bfloat16 h0 = __float2bfloat16(v.x), h1 = __float2bfloat16(v.y);
    __nv_bfloat16 h2 = __float2bfloat16(v.z), h3 = __float2bfloat16(v.w);
    __nv_bfloat16 l0 = __float2bfloat16(v.x - __bfloat162float(h0));
    __nv_bfloat16 l1 = __float2bfloat16(v.y - __bfloat162float(h1));
    __nv_bfloat16 l2 = __float2bfloat16(v.z - __bfloat162float(h2));
    __nv_bfloat16 l3 = __float2bfloat16(v.w - __bfloat162float(h3));

    uint2 uh, ul;
    uh.x = pack_bf2(h0, h1); uh.y = pack_bf2(h2, h3);
    ul.x = pack_bf2(l0, l1); ul.y = pack_bf2(l2, l3);
    reinterpret_cast<uint2*>(g_Ah)[(size_t)row * 128 + i] = uh;
    reinterpret_cast<uint2*>(g_Al)[(size_t)row * 128 + i] = ul;
}

// -------------------------------------------------------------------------
// Kernel 2: W hi/lo split (no transpose needed; ldmatrix.trans handles B).
// 65536 float4 chunks. grid 256 x 256 thr.
// -------------------------------------------------------------------------
__global__ void wsplit_kernel(const float* __restrict__ W)
{
    const int i = blockIdx.x * 256 + threadIdx.x;   // float4 index
    const float4 v = reinterpret_cast<const float4*>(W)[i];
    __nv_bfloat16 h0 = __float2bfloat16(v.x), h1 = __float2bfloat16(v.y);
    __nv_bfloat16 h2 = __float2bfloat16(v.z), h3 = __float2bfloat16(v.w);
    __nv_bfloat16 l0 = __float2bfloat16(v.x - __bfloat162float(h0));
    __nv_bfloat16 l1 = __float2bfloat16(v.y - __bfloat162float(h1));
    __nv_bfloat16 l2 = __float2bfloat16(v.z - __bfloat162float(h2));
    __nv_bfloat16 l3 = __float2bfloat16(v.w - __bfloat162float(h3));
    uint2 uh, ul;
    uh.x = pack_bf2(h0, h1); uh.y = pack_bf2(h2, h3);
    ul.x = pack_bf2(l0, l1); ul.y = pack_bf2(l2, l3);
    reinterpret_cast<uint2*>(g_Wh)[i] = uh;
    reinterpret_cast<uint2*>(g_Wl)[i] = ul;
}

// -------------------------------------------------------------------------
// Kernel 3: bf16 3-split GEMM via mma.sync.m16n8k16 + cp.async double buffer.
// CTA tile 128x128, BK=32, 8 warps (warp tile 64x32).
// SMEM per stage: Ah[128x32]@80B rows, Al same, Wh[32x128]@272B rows, Wl same.
// -------------------------------------------------------------------------
#define BKq       32
#define A_STRIDE  80          // bytes per A smem row (40 bf16, conflict-free)
#define W_STRIDE  272         // bytes per W smem row (136 bf16, conflict-free)
#define A_BUF     (128 * A_STRIDE)          // 10240
#define W_BUF     (BKq * W_STRIDE)          // 8704
#define STAGE_B   (2 * A_BUF + 2 * W_BUF)   // 37888
#define GEMM_SMEM (2 * STAGE_B)             // 75776

__global__ __launch_bounds__(256, 1)
void gemm_mma_kernel(const float* __restrict__ bias,
                     float* __restrict__ hidden)
{
    extern __shared__ char sm[];
    const uint32_t sbase = smem_u32(sm);

    const int tid  = threadIdx.x;
    const int n0   = blockIdx.x * 128;
    const int m0   = blockIdx.y * 128;
    const int w    = tid >> 5;
    const int lane = tid & 31;
    const int wm   = (w >> 2) * 64;    // warp row origin (0 / 64)
    const int wn   = (w & 3) * 32;     // warp col origin (0/32/64/96)

    float acc[4][4][4];
    #pragma unroll
    for (int a = 0; a < 4; a++)
        #pragma unroll
        for (int b = 0; b < 4; b++)
            #pragma unroll
            for (int c = 0; c < 4; c++) acc[a][b][c] = 0.f;

    // ---- stage loader ----
    auto load_stage = [&](int buf, int k0) {
        const uint32_t st = sbase + buf * STAGE_B;
        #pragma unroll
        for (int j = 0; j < 2; j++) {                 // A: 512 16B chunks (hi+lo)
            const int i = j * 256 + tid;
            const int row = i >> 2, c = i & 3;
            const uint32_t d = st + row * A_STRIDE + c * 16;
            const size_t src = (size_t)(m0 + row) * Kdim + k0 + c * 8;
            CP_ASYNC16(d,         g_Ah + src);
            CP_ASYNC16(d + A_BUF, g_Al + src);
        }
        #pragma unroll
        for (int j = 0; j < 2; j++) {                 // W: 512 16B chunks (hi+lo)
            const int i = j * 256 + tid;
            const int kr = i >> 4, ch = i & 15;
            const uint32_t d = st + 2 * A_BUF + kr * W_STRIDE + ch * 16;
            const size_t src = (size_t)(k0 + kr) * Hq + n0 + ch * 8;
            CP_ASYNC16(d,         g_Wh + src);
            CP_ASYNC16(d + W_BUF, g_Wl + src);
        }
        CP_COMMIT();
    };

    load_stage(0, 0);

    #pragma unroll 1
    for (int s = 0; s < 16; s++) {
        if (s + 1 < 16) load_stage((s + 1) & 1, (s + 1) * BKq);
        if (s + 1 < 16) CP_WAIT1(); else CP_WAIT0();
        __syncthreads();

        const uint32_t st   = sbase + (s & 1) * STAGE_B;
        const uint32_t Ah_b = st;
        const uint32_t Wh_b = st + 2 * A_BUF;

        #pragma unroll
        for (int kk = 0; kk < 2; kk++) {
            const int k16 = kk * 16;
            uint32_t aH[4][4], aL[4][4], bH[2][4], bL[2][4];

            const int arow  = lane & 15;
            const int acolB = (k16 + ((lane >> 4) << 3)) * 2;
            #pragma unroll
            for (int im = 0; im < 4; im++) {
                const uint32_t ad = Ah_b + (wm + im * 16 + arow) * A_STRIDE + acolB;
                LDSM4(aH[im], ad);
                LDSM4(aL[im], ad + A_BUF);
            }
            const int brow = k16 + (lane & 15);
            #pragma unroll
            for (int in = 0; in < 2; in++) {
                const uint32_t bd = Wh_b + brow * W_STRIDE
                                  + (wn + in * 16 + ((lane >> 4) << 3)) * 2;
                LDSM4T(bH[in], bd);
                LDSM4T(bL[in], bd + W_BUF);
            }

            #pragma unroll
            for (int im = 0; im < 4; im++)
                #pragma unroll
                for (int in = 0; in < 2; in++) {
                    MMA16816(acc[im][2 * in],     aH[im], bH[in][0], bH[in][1]);
                    MMA16816(acc[im][2 * in + 1], aH[im], bH[in][2], bH[in][3]);
                    MMA16816(acc[im][2 * in],     aH[im], bL[in][0], bL[in][1]);
                    MMA16816(acc[im][2 * in + 1], aH[im], bL[in][2], bL[in][3]);
                    MMA16816(acc[im][2 * in],     aL[im], bH[in][0], bH[in][1]);
                    MMA16816(acc[im][2 * in + 1], aL[im], bH[in][2], bH[in][3]);
                }
        }
        __syncthreads();
    }

    // ---- epilogue: + bias, store (guard M tail; hidden is followed by
    //      token_lengths/tokens in d_out, so no overshoot allowed) ----
    #pragma unroll
    for (int im = 0; im < 4; im++) {
        const int gm = m0 + wm + im * 16 + (lane >> 2);
        #pragma unroll
        for (int j = 0; j < 4; j++) {
            const int gn = n0 + wn + j * 8 + 2 * (lane & 3);
            const float b0 = __ldg(bias + gn), b1 = __ldg(bias + gn + 1);
            if (gm < Mrows) {
                float2 v = make_float2(acc[im][j][0] + b0, acc[im][j][1] + b1);
                *reinterpret_cast<float2*>(hidden + (size_t)gm * Hq + gn) = v;
            }
            if (gm + 8 < Mrows) {
                float2 v = make_float2(acc[im][j][2] + b0, acc[im][j][3] + b1);
                *reinterpret_cast<float2*>(hidden + (size_t)(gm + 8) * Hq + gn) = v;
            }
        }
    }
}

// -------------------------------------------------------------------------
// Kernel 4: in-place RMSNorm per 512-row. 1 block / row, 128 thr.
// -------------------------------------------------------------------------
__global__ void rmsnorm_kernel(float* __restrict__ h,
                               const float* __restrict__ scale)
{
    const int row = blockIdx.x;
    float4* hp = reinterpret_cast<float4*>(h + (size_t)row * Hq);
    const int i = threadIdx.x;

    float4 v = hp[i];
    float ss = v.x * v.x + v.y * v.y + v.z * v.z + v.w * v.w;
    #pragma unroll
    for (int o = 16; o > 0; o >>= 1)
        ss += __shfl_down_sync(0xffffffffu, ss, o);

    __shared__ float red[4];
    if ((i & 31) == 0) red[i >> 5] = ss;
    __syncthreads();
    const float tot = red[0] + red[1] + red[2] + red[3];
    const float inv = rsqrtf(tot * (1.0f / 512.0f) + 1e-6f);

    const float4 s = reinterpret_cast<const float4*>(scale)[i];
    v.x *= inv * s.x;  v.y *= inv * s.y;
    v.z *= inv * s.z;  v.w *= inv * s.w;
    hp[i] = v;
}

// -------------------------------------------------------------------------
// launch. output: [hidden M*512][token_lengths 32][tokens M*512]
// -------------------------------------------------------------------------
extern "C" void kernel_launch(void* const* d_in, const int* in_sizes, int n_in,
                              void* d_out, int out_size)
{
    const float* x       = (const float*)d_in[0];
    const int*   lengths = (const int*)  d_in[1];
    const float* W       = (const float*)d_in[2];
    const float* bias    = (const float*)d_in[3];
    const float* scale   = (const float*)d_in[4];

    float* out        = (float*)d_out;
    float* out_hidden = out;
    float* out_len    = out + (size_t)Mrows * Hq;
    float* out_tokens = out + (size_t)Mrows * Hq + Bq;

    cudaFuncSetAttribute(gemm_mma_kernel,
                         cudaFuncAttributeMaxDynamicSharedMemorySize, GEMM_SMEM);

    gather_split_kernel<<<Mpad, 128>>>(x, lengths, out_tokens, out_len);
    wsplit_kernel<<<256, 256>>>(W);
    gemm_mma_kernel<<<dim3(4, 256), 256, GEMM_SMEM>>>(bias, out_hidden);
    rmsnorm_kernel<<<Mrows, 128>>>(out_hidden, scale);
}

// round 4
// speedup vs baseline: 2.9049x; 1.1521x over previous
#include <cuda_runtime.h>
#include <cuda_bf16.h>
#include <cstdint>

// ---------------- problem constants ----------------
#define Bq      32
#define Sq      4096
#define Dq      64
#define Pq      8
#define STRIDEq 4
#define Hq      512
#define Tq      1023
#define Mrows   (Bq * Tq)     // 32736
#define Mpad    32768
#define Kdim    512

// ---------------- device-global scratch (allocation-free rule) ----------
__device__ __align__(256) __nv_bfloat16 g_Ah[(size_t)Mpad * Kdim];
__device__ __align__(256) __nv_bfloat16 g_Al[(size_t)Mpad * Kdim];
__device__ __align__(256) __nv_bfloat16 g_Wh[Kdim * Hq];   // hi split, [k][h]
__device__ __align__(256) __nv_bfloat16 g_Wl[Kdim * Hq];   // lo split, [k][h]

// ---------------- PTX helpers (plain sm_80-class PTX only) -------------
__device__ __forceinline__ uint32_t smem_u32(const void* p) {
    uint32_t a;
    asm("{ .reg .u64 t; cvta.to.shared.u64 t, %1; cvt.u32.u64 %0, t; }" : "=r"(a) : "l"(p));
    return a;
}

#define CP_ASYNC16(dst, src) \
    asm volatile("cp.async.cg.shared.global [%0], [%1], 16;" \
                 :: "r"((uint32_t)(dst)), "l"(__cvta_generic_to_global(src)) : "memory")
#define CP_COMMIT()  asm volatile("cp.async.commit_group;" ::: "memory")
#define CP_WAIT0()   asm volatile("cp.async.wait_group 0;" ::: "memory")

#define LDSM4(r, addr) \
    asm volatile("ldmatrix.sync.aligned.m8n8.x4.shared.b16 {%0,%1,%2,%3}, [%4];" \
                 : "=r"((r)[0]), "=r"((r)[1]), "=r"((r)[2]), "=r"((r)[3]) : "r"(addr))
#define LDSM4T(r, addr) \
    asm volatile("ldmatrix.sync.aligned.m8n8.x4.trans.shared.b16 {%0,%1,%2,%3}, [%4];" \
                 : "=r"((r)[0]), "=r"((r)[1]), "=r"((r)[2]), "=r"((r)[3]) : "r"(addr))

#define MMA16816(d, a, b0_, b1_) \
    asm volatile("mma.sync.aligned.m16n8k16.row.col.f32.bf16.bf16.f32 " \
                 "{%0,%1,%2,%3}, {%4,%5,%6,%7}, {%8,%9}, {%0,%1,%2,%3};" \
                 : "+f"((d)[0]), "+f"((d)[1]), "+f"((d)[2]), "+f"((d)[3]) \
                 : "r"((a)[0]), "r"((a)[1]), "r"((a)[2]), "r"((a)[3]), \
                   "r"(b0_), "r"(b1_))

__device__ __forceinline__ uint32_t pack_bf2(__nv_bfloat16 a, __nv_bfloat16 b) {
    __nv_bfloat162 t = __halves2bfloat162(a, b);
    return *reinterpret_cast<uint32_t*>(&t);
}

// -------------------------------------------------------------------------
// Kernel 1: gather tokens + bf16 hi/lo split of A. Grid Mpad, 128 thr.
// -------------------------------------------------------------------------
__global__ void gather_split_kernel(const float* __restrict__ x,
                                    const int*   __restrict__ lengths,
                                    float* __restrict__ tok,
                                    float* __restrict__ out_len)
{
    const int row = blockIdx.x;
    const int i   = threadIdx.x;          // float4 index within 512-row
    float4 v = make_float4(0.f, 0.f, 0.f, 0.f);

    if (row < Mrows) {
        const int b = row / Tq;
        const int t = row - b * Tq;
        const int ntok = (lengths[b] - Pq) / STRIDEq + 1;
        if (t < ntok) {
            const int p  = i >> 4;
            const int d4 = i & 15;
            v = reinterpret_cast<const float4*>(
                    x + ((size_t)b * Sq + (size_t)t * STRIDEq + p) * Dq)[d4];
        }
        reinterpret_cast<float4*>(tok + (size_t)row * Kdim)[i] = v;
        if (row == 0 && i < Bq)
            out_len[i] = (float)((lengths[i] - Pq) / STRIDEq + 1);
    }

    __nv_bfloat16 h0 = __float2bfloat16(v.x), h1 = __float2bfloat16(v.y);
    __nv_bfloat16 h2 = __float2bfloat16(v.z), h3 = __float2bfloat16(v.w);
    __nv_bfloat16 l0 = __float2bfloat16(v.x - __bfloat162float(h0));
    __nv_bfloat16 l1 = __float2bfloat16(v.y - __bfloat162float(h1));
    __nv_bfloat16 l2 = __float2bfloat16(v.z - __bfloat162float(h2));
    __nv_bfloat16 l3 = __float2bfloat16(v.w - __bfloat162float(h3));

    uint2 uh, ul;
    uh.x = pack_bf2(h0, h1); uh.y = pack_bf2(h2, h3);
    ul.x = pack_bf2(l0, l1); ul.y = pack_bf2(l2, l3);
    reinterpret_cast<uint2*>(g_Ah)[(size_t)row * 128 + i] = uh;
    reinterpret_cast<uint2*>(g_Al)[(size_t)row * 128 + i] = ul;
}

// -------------------------------------------------------------------------
// Kernel 2: W hi/lo split.
// -------------------------------------------------------------------------
__global__ void wsplit_kernel(const float* __restrict__ W)
{
    const int i = blockIdx.x * 256 + threadIdx.x;   // float4 index
    const float4 v = reinterpret_cast<const float4*>(W)[i];
    __nv_bfloat16 h0 = __float2bfloat16(v.x), h1 = __float2bfloat16(v.y);
    __nv_bfloat16 h2 = __float2bfloat16(v.z), h3 = __float2bfloat16(v.w);
    __nv_bfloat16 l0 = __float2bfloat16(v.x - __bfloat162float(h0));
    __nv_bfloat16 l1 = __float2bfloat16(v.y - __bfloat162float(h1));
    __nv_bfloat16 l2 = __float2bfloat16(v.z - __bfloat162float(h2));
    __nv_bfloat16 l3 = __float2bfloat16(v.w - __bfloat162float(h3));
    uint2 uh, ul;
    uh.x = pack_bf2(h0, h1); uh.y = pack_bf2(h2, h3);
    ul.x = pack_bf2(l0, l1); ul.y = pack_bf2(l2, l3);
    reinterpret_cast<uint2*>(g_Wh)[i] = uh;
    reinterpret_cast<uint2*>(g_Wl)[i] = ul;
}

// -------------------------------------------------------------------------
// Kernel 3: bf16 3-split GEMM via mma.sync.m16n8k16 + cp.async double buffer.
// CTA 128x128, BK=32, 8 warps (warp tile 64x32). ONE barrier per stage,
// loads issued after the barrier so they overlap MMA. Occupancy 2.
// -------------------------------------------------------------------------
#define BKq       32
#define A_STRIDE  80
#define W_STRIDE  272
#define A_BUF     (128 * A_STRIDE)          // 10240
#define W_BUF     (BKq * W_STRIDE)          // 8704
#define STAGE_B   (2 * A_BUF + 2 * W_BUF)   // 37888
#define GEMM_SMEM (2 * STAGE_B)             // 75776 (x2 CTAs = 151.5KB/SM)

__global__ __launch_bounds__(256, 2)
void gemm_mma_kernel(const float* __restrict__ bias,
                     float* __restrict__ hidden)
{
    extern __shared__ char sm[];
    const uint32_t sbase = smem_u32(sm);

    const int tid  = threadIdx.x;
    const int n0   = blockIdx.x * 128;
    const int m0   = blockIdx.y * 128;
    const int w    = tid >> 5;
    const int lane = tid & 31;
    const int wm   = (w >> 2) * 64;
    const int wn   = (w & 3) * 32;

    float acc[4][4][4];
    #pragma unroll
    for (int a = 0; a < 4; a++)
        #pragma unroll
        for (int b = 0; b < 4; b++)
            #pragma unroll
            for (int c = 0; c < 4; c++) acc[a][b][c] = 0.f;

    auto load_stage = [&](int buf, int k0) {
        const uint32_t st = sbase + buf * STAGE_B;
        #pragma unroll
        for (int j = 0; j < 2; j++) {                 // A hi+lo
            const int i = j * 256 + tid;
            const int row = i >> 2, c = i & 3;
            const uint32_t d = st + row * A_STRIDE + c * 16;
            const size_t src = (size_t)(m0 + row) * Kdim + k0 + c * 8;
            CP_ASYNC16(d,         g_Ah + src);
            CP_ASYNC16(d + A_BUF, g_Al + src);
        }
        #pragma unroll
        for (int j = 0; j < 2; j++) {                 // W hi+lo
            const int i = j * 256 + tid;
            const int kr = i >> 4, ch = i & 15;
            const uint32_t d = st + 2 * A_BUF + kr * W_STRIDE + ch * 16;
            const size_t src = (size_t)(k0 + kr) * Hq + n0 + ch * 8;
            CP_ASYNC16(d,         g_Wh + src);
            CP_ASYNC16(d + W_BUF, g_Wl + src);
        }
        CP_COMMIT();
    };

    load_stage(0, 0);

    #pragma unroll 1
    for (int s = 0; s < 16; s++) {
        CP_WAIT0();            // own stage-s loads complete
        __syncthreads();       // publish stage s; prior readers of buf (s+1)&1 done
        if (s + 1 < 16) load_stage((s + 1) & 1, (s + 1) * BKq);   // overlaps MMA

        const uint32_t st   = sbase + (s & 1) * STAGE_B;
        const uint32_t Ah_b = st;
        const uint32_t Wh_b = st + 2 * A_BUF;

        #pragma unroll
        for (int kk = 0; kk < 2; kk++) {
            const int k16 = kk * 16;
            uint32_t aH[4][4], aL[4][4], bH[2][4], bL[2][4];

            const int arow  = lane & 15;
            const int acolB = (k16 + ((lane >> 4) << 3)) * 2;
            #pragma unroll
            for (int im = 0; im < 4; im++) {
                const uint32_t ad = Ah_b + (wm + im * 16 + arow) * A_STRIDE + acolB;
                LDSM4(aH[im], ad);
                LDSM4(aL[im], ad + A_BUF);
            }
            const int brow = k16 + (lane & 15);
            #pragma unroll
            for (int in = 0; in < 2; in++) {
                const uint32_t bd = Wh_b + brow * W_STRIDE
                                  + (wn + in * 16 + ((lane >> 4) << 3)) * 2;
                LDSM4T(bH[in], bd);
                LDSM4T(bL[in], bd + W_BUF);
            }

            #pragma unroll
            for (int im = 0; im < 4; im++)
                #pragma unroll
                for (int in = 0; in < 2; in++) {
                    MMA16816(acc[im][2 * in],     aH[im], bH[in][0], bH[in][1]);
                    MMA16816(acc[im][2 * in + 1], aH[im], bH[in][2], bH[in][3]);
                    MMA16816(acc[im][2 * in],     aH[im], bL[in][0], bL[in][1]);
                    MMA16816(acc[im][2 * in + 1], aH[im], bL[in][2], bL[in][3]);
                    MMA16816(acc[im][2 * in],     aL[im], bH[in][0], bH[in][1]);
                    MMA16816(acc[im][2 * in + 1], aL[im], bH[in][2], bH[in][3]);
                }
        }
    }

    // ---- epilogue: + bias, guarded stores ----
    #pragma unroll
    for (int im = 0; im < 4; im++) {
        const int gm = m0 + wm + im * 16 + (lane >> 2);
        #pragma unroll
        for (int j = 0; j < 4; j++) {
            const int gn = n0 + wn + j * 8 + 2 * (lane & 3);
            const float b0 = __ldg(bias + gn), b1 = __ldg(bias + gn + 1);
            if (gm < Mrows) {
                float2 v = make_float2(acc[im][j][0] + b0, acc[im][j][1] + b1);
                *reinterpret_cast<float2*>(hidden + (size_t)gm * Hq + gn) = v;
            }
            if (gm + 8 < Mrows) {
                float2 v = make_float2(acc[im][j][2] + b0, acc[im][j][3] + b1);
                *reinterpret_cast<float2*>(hidden + (size_t)(gm + 8) * Hq + gn) = v;
            }
        }
    }
}

// -------------------------------------------------------------------------
// Kernel 4: in-place RMSNorm. 256-thread blocks, 2 rows per block.
// -------------------------------------------------------------------------
__global__ __launch_bounds__(256)
void rmsnorm_kernel(float* __restrict__ h,
                    const float* __restrict__ scale)
{
    const int rloc = threadIdx.x >> 7;            // 0/1
    const int row  = blockIdx.x * 2 + rloc;
    const int i    = threadIdx.x & 127;           // float4 idx in row
    const int wrp  = threadIdx.x >> 5;            // 0..7

    float4* hp = reinterpret_cast<float4*>(h + (size_t)row * Hq);
    float4 v = hp[i];
    float ss = v.x * v.x + v.y * v.y + v.z * v.z + v.w * v.w;
    #pragma unroll
    for (int o = 16; o > 0; o >>= 1)
        ss += __shfl_down_sync(0xffffffffu, ss, o);

    __shared__ float red[8];
    if ((threadIdx.x & 31) == 0) red[wrp] = ss;
    __syncthreads();
    const int rb = rloc * 4;
    const float tot = red[rb] + red[rb + 1] + red[rb + 2] + red[rb + 3];
    const float inv = rsqrtf(tot * (1.0f / 512.0f) + 1e-6f);

    const float4 s = reinterpret_cast<const float4*>(scale)[i];
    v.x *= inv * s.x;  v.y *= inv * s.y;
    v.z *= inv * s.z;  v.w *= inv * s.w;
    hp[i] = v;
}

// -------------------------------------------------------------------------
// launch. output: [hidden M*512][token_lengths 32][tokens M*512]
// -------------------------------------------------------------------------
extern "C" void kernel_launch(void* const* d_in, const int* in_sizes, int n_in,
                              void* d_out, int out_size)
{
    const float* x       = (const float*)d_in[0];
    const int*   lengths = (const int*)  d_in[1];
    const float* W       = (const float*)d_in[2];
    const float* bias    = (const float*)d_in[3];
    const float* scale   = (const float*)d_in[4];

    float* out        = (float*)d_out;
    float* out_hidden = out;
    float* out_len    = out + (size_t)Mrows * Hq;
    float* out_tokens = out + (size_t)Mrows * Hq + Bq;

    cudaFuncSetAttribute(gemm_mma_kernel,
                         cudaFuncAttributeMaxDynamicSharedMemorySize, GEMM_SMEM);

    gather_split_kernel<<<Mpad, 128>>>(x, lengths, out_tokens, out_len);
    wsplit_kernel<<<256, 256>>>(W);
    gemm_mma_kernel<<<dim3(4, 256), 256, GEMM_SMEM>>>(bias, out_hidden);
    rmsnorm_kernel<<<Mrows / 2, 256>>>(out_hidden, scale);
}

// round 5
// speedup vs baseline: 2.9821x; 1.0266x over previous
#include <cuda_runtime.h>
#include <cuda_bf16.h>
#include <cstdint>

// ---------------- problem constants ----------------
#define Bq      32
#define Sq      4096
#define Dq      64
#define Pq      8
#define STRIDEq 4
#define Hq      512
#define Tq      1023
#define Mrows   (Bq * Tq)     // 32736
#define Mpad    32768
#define Kdim    512

// ---------------- device-global scratch (allocation-free rule) ----------
__device__ __align__(256) __nv_bfloat16 g_Ah[(size_t)Mpad * Kdim];
__device__ __align__(256) __nv_bfloat16 g_Al[(size_t)Mpad * Kdim];
__device__ __align__(256) __nv_bfloat16 g_Wh[Kdim * Hq];   // hi split, [k][h]
__device__ __align__(256) __nv_bfloat16 g_Wl[Kdim * Hq];   // lo split, [k][h]

// ---------------- PTX helpers (plain sm_80-class PTX only) -------------
__device__ __forceinline__ uint32_t smem_u32(const void* p) {
    uint32_t a;
    asm("{ .reg .u64 t; cvta.to.shared.u64 t, %1; cvt.u32.u64 %0, t; }" : "=r"(a) : "l"(p));
    return a;
}

#define CP_ASYNC16(dst, src) \
    asm volatile("cp.async.cg.shared.global [%0], [%1], 16;" \
                 :: "r"((uint32_t)(dst)), "l"(__cvta_generic_to_global(src)) : "memory")
#define CP_COMMIT()  asm volatile("cp.async.commit_group;" ::: "memory")
#define CP_WAIT0()   asm volatile("cp.async.wait_group 0;" ::: "memory")

#define LDSM4(r, addr) \
    asm volatile("ldmatrix.sync.aligned.m8n8.x4.shared.b16 {%0,%1,%2,%3}, [%4];" \
                 : "=r"((r)[0]), "=r"((r)[1]), "=r"((r)[2]), "=r"((r)[3]) : "r"(addr))
#define LDSM4T(r, addr) \
    asm volatile("ldmatrix.sync.aligned.m8n8.x4.trans.shared.b16 {%0,%1,%2,%3}, [%4];" \
                 : "=r"((r)[0]), "=r"((r)[1]), "=r"((r)[2]), "=r"((r)[3]) : "r"(addr))

#define MMA16816(d, a, b0_, b1_) \
    asm volatile("mma.sync.aligned.m16n8k16.row.col.f32.bf16.bf16.f32 " \
                 "{%0,%1,%2,%3}, {%4,%5,%6,%7}, {%8,%9}, {%0,%1,%2,%3};" \
                 : "+f"((d)[0]), "+f"((d)[1]), "+f"((d)[2]), "+f"((d)[3]) \
                 : "r"((a)[0]), "r"((a)[1]), "r"((a)[2]), "r"((a)[3]), \
                   "r"(b0_), "r"(b1_))

__device__ __forceinline__ uint32_t pack_bf2(__nv_bfloat16 a, __nv_bfloat16 b) {
    __nv_bfloat162 t = __halves2bfloat162(a, b);
    return *reinterpret_cast<uint32_t*>(&t);
}

// -------------------------------------------------------------------------
// Kernel 1: gather tokens + bf16 hi/lo split of A. Grid Mpad, 128 thr.
// -------------------------------------------------------------------------
__global__ void gather_split_kernel(const float* __restrict__ x,
                                    const int*   __restrict__ lengths,
                                    float* __restrict__ tok,
                                    float* __restrict__ out_len)
{
    const int row = blockIdx.x;
    const int i   = threadIdx.x;          // float4 index within 512-row
    float4 v = make_float4(0.f, 0.f, 0.f, 0.f);

    if (row < Mrows) {
        const int b = row / Tq;
        const int t = row - b * Tq;
        const int ntok = (lengths[b] - Pq) / STRIDEq + 1;
        if (t < ntok) {
            const int p  = i >> 4;
            const int d4 = i & 15;
            v = reinterpret_cast<const float4*>(
                    x + ((size_t)b * Sq + (size_t)t * STRIDEq + p) * Dq)[d4];
        }
        reinterpret_cast<float4*>(tok + (size_t)row * Kdim)[i] = v;
        if (row == 0 && i < Bq)
            out_len[i] = (float)((lengths[i] - Pq) / STRIDEq + 1);
    }

    __nv_bfloat16 h0 = __float2bfloat16(v.x), h1 = __float2bfloat16(v.y);
    __nv_bfloat16 h2 = __float2bfloat16(v.z), h3 = __float2bfloat16(v.w);
    __nv_bfloat16 l0 = __float2bfloat16(v.x - __bfloat162float(h0));
    __nv_bfloat16 l1 = __float2bfloat16(v.y - __bfloat162float(h1));
    __nv_bfloat16 l2 = __float2bfloat16(v.z - __bfloat162float(h2));
    __nv_bfloat16 l3 = __float2bfloat16(v.w - __bfloat162float(h3));

    uint2 uh, ul;
    uh.x = pack_bf2(h0, h1); uh.y = pack_bf2(h2, h3);
    ul.x = pack_bf2(l0, l1); ul.y = pack_bf2(l2, l3);
    reinterpret_cast<uint2*>(g_Ah)[(size_t)row * 128 + i] = uh;
    reinterpret_cast<uint2*>(g_Al)[(size_t)row * 128 + i] = ul;
}

// -------------------------------------------------------------------------
// Kernel 2: W hi/lo split.
// -------------------------------------------------------------------------
__global__ void wsplit_kernel(const float* __restrict__ W)
{
    const int i = blockIdx.x * 256 + threadIdx.x;   // float4 index
    const float4 v = reinterpret_cast<const float4*>(W)[i];
    __nv_bfloat16 h0 = __float2bfloat16(v.x), h1 = __float2bfloat16(v.y);
    __nv_bfloat16 h2 = __float2bfloat16(v.z), h3 = __float2bfloat16(v.w);
    __nv_bfloat16 l0 = __float2bfloat16(v.x - __bfloat162float(h0));
    __nv_bfloat16 l1 = __float2bfloat16(v.y - __bfloat162float(h1));
    __nv_bfloat16 l2 = __float2bfloat16(v.z - __bfloat162float(h2));
    __nv_bfloat16 l3 = __float2bfloat16(v.w - __bfloat162float(h3));
    uint2 uh, ul;
    uh.x = pack_bf2(h0, h1); uh.y = pack_bf2(h2, h3);
    ul.x = pack_bf2(l0, l1); ul.y = pack_bf2(l2, l3);
    reinterpret_cast<uint2*>(g_Wh)[i] = uh;
    reinterpret_cast<uint2*>(g_Wl)[i] = ul;
}

// -------------------------------------------------------------------------
// Kernel 3: bf16 3-split GEMM via mma.sync.m16n8k16 + cp.async double buffer.
// CTA 128x128, BK=32, 8 warps (warp tile 64x32), occ 2, 1 barrier/stage.
// Inner loop = sequential split batches to keep live regs ~100 (no spills).
// -------------------------------------------------------------------------
#define BKq       32
#define A_STRIDE  80
#define W_STRIDE  272
#define A_BUF     (128 * A_STRIDE)          // 10240
#define W_BUF     (BKq * W_STRIDE)          // 8704
#define STAGE_B   (2 * A_BUF + 2 * W_BUF)   // 37888
#define GEMM_SMEM (2 * STAGE_B)             // 75776 (x2 CTAs = 151.5KB/SM)

__global__ __launch_bounds__(256, 2)
void gemm_mma_kernel(const float* __restrict__ bias,
                     float* __restrict__ hidden)
{
    extern __shared__ char sm[];
    const uint32_t sbase = smem_u32(sm);

    const int tid  = threadIdx.x;
    const int n0   = blockIdx.x * 128;
    const int m0   = blockIdx.y * 128;
    const int w    = tid >> 5;
    const int lane = tid & 31;
    const int wm   = (w >> 2) * 64;
    const int wn   = (w & 3) * 32;

    float acc[4][4][4];
    #pragma unroll
    for (int a = 0; a < 4; a++)
        #pragma unroll
        for (int b = 0; b < 4; b++)
            #pragma unroll
            for (int c = 0; c < 4; c++) acc[a][b][c] = 0.f;

    auto load_stage = [&](int buf, int k0) {
        const uint32_t st = sbase + buf * STAGE_B;
        #pragma unroll
        for (int j = 0; j < 2; j++) {                 // A hi+lo
            const int i = j * 256 + tid;
            const int row = i >> 2, c = i & 3;
            const uint32_t d = st + row * A_STRIDE + c * 16;
            const size_t src = (size_t)(m0 + row) * Kdim + k0 + c * 8;
            CP_ASYNC16(d,         g_Ah + src);
            CP_ASYNC16(d + A_BUF, g_Al + src);
        }
        #pragma unroll
        for (int j = 0; j < 2; j++) {                 // W hi+lo
            const int i = j * 256 + tid;
            const int kr = i >> 4, ch = i & 15;
            const uint32_t d = st + 2 * A_BUF + kr * W_STRIDE + ch * 16;
            const size_t src = (size_t)(k0 + kr) * Hq + n0 + ch * 8;
            CP_ASYNC16(d,         g_Wh + src);
            CP_ASYNC16(d + W_BUF, g_Wl + src);
        }
        CP_COMMIT();
    };

    load_stage(0, 0);

    #pragma unroll 1
    for (int s = 0; s < 16; s++) {
        CP_WAIT0();            // own stage-s loads complete
        __syncthreads();       // publish stage s; prior readers of other buf done
        if (s + 1 < 16) load_stage((s + 1) & 1, (s + 1) * BKq);   // overlaps MMA

        const uint32_t st   = sbase + (s & 1) * STAGE_B;
        const uint32_t Ah_b = st;
        const uint32_t Wh_b = st + 2 * A_BUF;

        #pragma unroll
        for (int kk = 0; kk < 2; kk++) {
            const int k16 = kk * 16;
            uint32_t aX[4][4], bH[2][4], bL[2][4];

            const int arow  = lane & 15;
            const int acolB = (k16 + ((lane >> 4) << 3)) * 2;
            const int brow  = k16 + (lane & 15);

            // batch 0 operands: A-hi, B-hi, B-lo
            #pragma unroll
            for (int im = 0; im < 4; im++)
                LDSM4(aX[im], Ah_b + (wm + im * 16 + arow) * A_STRIDE + acolB);
            #pragma unroll
            for (int in = 0; in < 2; in++) {
                const uint32_t bd = Wh_b + brow * W_STRIDE
                                  + (wn + in * 16 + ((lane >> 4) << 3)) * 2;
                LDSM4T(bH[in], bd);
                LDSM4T(bL[in], bd + W_BUF);
            }

            // hi * hi
            #pragma unroll
            for (int im = 0; im < 4; im++)
                #pragma unroll
                for (int in = 0; in < 2; in++) {
                    MMA16816(acc[im][2 * in],     aX[im], bH[in][0], bH[in][1]);
                    MMA16816(acc[im][2 * in + 1], aX[im], bH[in][2], bH[in][3]);
                }
            // hi * lo
            #pragma unroll
            for (int im = 0; im < 4; im++)
                #pragma unroll
                for (int in = 0; in < 2; in++) {
                    MMA16816(acc[im][2 * in],     aX[im], bL[in][0], bL[in][1]);
                    MMA16816(acc[im][2 * in + 1], aX[im], bL[in][2], bL[in][3]);
                }
            // reload A-lo into same regs (aH dead), then lo * hi
            #pragma unroll
            for (int im = 0; im < 4; im++)
                LDSM4(aX[im], Ah_b + A_BUF + (wm + im * 16 + arow) * A_STRIDE + acolB);
            #pragma unroll
            for (int im = 0; im < 4; im++)
                #pragma unroll
                for (int in = 0; in < 2; in++) {
                    MMA16816(acc[im][2 * in],     aX[im], bH[in][0], bH[in][1]);
                    MMA16816(acc[im][2 * in + 1], aX[im], bH[in][2], bH[in][3]);
                }
        }
    }

    // ---- epilogue: + bias, guarded stores ----
    #pragma unroll
    for (int im = 0; im < 4; im++) {
        const int gm = m0 + wm + im * 16 + (lane >> 2);
        #pragma unroll
        for (int j = 0; j < 4; j++) {
            const int gn = n0 + wn + j * 8 + 2 * (lane & 3);
            const float b0 = __ldg(bias + gn), b1 = __ldg(bias + gn + 1);
            if (gm < Mrows) {
                float2 v = make_float2(acc[im][j][0] + b0, acc[im][j][1] + b1);
                *reinterpret_cast<float2*>(hidden + (size_t)gm * Hq + gn) = v;
            }
            if (gm + 8 < Mrows) {
                float2 v = make_float2(acc[im][j][2] + b0, acc[im][j][3] + b1);
                *reinterpret_cast<float2*>(hidden + (size_t)(gm + 8) * Hq + gn) = v;
            }
        }
    }
}

// -------------------------------------------------------------------------
// Kernel 4: in-place RMSNorm. 256-thread blocks, 2 rows per block.
// -------------------------------------------------------------------------
__global__ __launch_bounds__(256)
void rmsnorm_kernel(float* __restrict__ h,
                    const float* __restrict__ scale)
{
    const int rloc = threadIdx.x >> 7;            // 0/1
    const int row  = blockIdx.x * 2 + rloc;
    const int i    = threadIdx.x & 127;           // float4 idx in row
    const int wrp  = threadIdx.x >> 5;            // 0..7

    float4* hp = reinterpret_cast<float4*>(h + (size_t)row * Hq);
    float4 v = hp[i];
    float ss = v.x * v.x + v.y * v.y + v.z * v.z + v.w * v.w;
    #pragma unroll
    for (int o = 16; o > 0; o >>= 1)
        ss += __shfl_down_sync(0xffffffffu, ss, o);

    __shared__ float red[8];
    if ((threadIdx.x & 31) == 0) red[wrp] = ss;
    __syncthreads();
    const int rb = rloc * 4;
    const float tot = red[rb] + red[rb + 1] + red[rb + 2] + red[rb + 3];
    const float inv = rsqrtf(tot * (1.0f / 512.0f) + 1e-6f);

    const float4 s = reinterpret_cast<const float4*>(scale)[i];
    v.x *= inv * s.x;  v.y *= inv * s.y;
    v.z *= inv * s.z;  v.w *= inv * s.w;
    hp[i] = v;
}

// -------------------------------------------------------------------------
// launch. output: [hidden M*512][token_lengths 32][tokens M*512]
// -------------------------------------------------------------------------
extern "C" void kernel_launch(void* const* d_in, const int* in_sizes, int n_in,
                              void* d_out, int out_size)
{
    const float* x       = (const float*)d_in[0];
    const int*   lengths = (const int*)  d_in[1];
    const float* W       = (const float*)d_in[2];
    const float* bias    = (const float*)d_in[3];
    const float* scale   = (const float*)d_in[4];

    float* out        = (float*)d_out;
    float* out_hidden = out;
    float* out_len    = out + (size_t)Mrows * Hq;
    float* out_tokens = out + (size_t)Mrows * Hq + Bq;

    cudaFuncSetAttribute(gemm_mma_kernel,
                         cudaFuncAttributeMaxDynamicSharedMemorySize, GEMM_SMEM);

    gather_split_kernel<<<Mpad, 128>>>(x, lengths, out_tokens, out_len);
    wsplit_kernel<<<256, 256>>>(W);
    gemm_mma_kernel<<<dim3(4, 256), 256, GEMM_SMEM>>>(bias, out_hidden);
    rmsnorm_kernel<<<Mrows / 2, 256>>>(out_hidden, scale);
}